// round 2
// baseline (speedup 1.0000x reference)
#include <cuda_runtime.h>

// ---------------------------------------------------------------------------
// RelativeDifferenceLoss: mean over N of (y==0 ? |x-y| : |x-y|/y)
// N = 2^25 fp32 elements per input. Pure HBM-streaming reduction.
// ---------------------------------------------------------------------------

#define NBLOCKS   2368          // 148 SMs * 16
#define NTHREADS  256

__device__ float g_partials[NBLOCKS];

__device__ __forceinline__ float rel_term(float x, float y) {
    float ad = fabsf(x - y);
    // match reference: if y==0 -> ad, else ad / y  (signed y!)
    return (y == 0.0f) ? ad : __fdividef(ad, y);
}

__global__ void __launch_bounds__(NTHREADS, 1)
rdl_partial_kernel(const float* __restrict__ x,
                   const float* __restrict__ y,
                   int n4)   // number of float4 chunks
{
    const float4* __restrict__ x4 = (const float4*)x;
    const float4* __restrict__ y4 = (const float4*)y;

    float acc = 0.0f;
    int stride = gridDim.x * blockDim.x;
    for (int i = blockIdx.x * blockDim.x + threadIdx.x; i < n4; i += stride) {
        float4 xv = x4[i];
        float4 yv = y4[i];
        acc += rel_term(xv.x, yv.x);
        acc += rel_term(xv.y, yv.y);
        acc += rel_term(xv.z, yv.z);
        acc += rel_term(xv.w, yv.w);
    }

    // warp reduce
    #pragma unroll
    for (int off = 16; off > 0; off >>= 1)
        acc += __shfl_down_sync(0xFFFFFFFFu, acc, off);

    __shared__ float s_warp[NTHREADS / 32];
    int lane = threadIdx.x & 31;
    int wid  = threadIdx.x >> 5;
    if (lane == 0) s_warp[wid] = acc;
    __syncthreads();

    if (wid == 0) {
        float v = (lane < NTHREADS / 32) ? s_warp[lane] : 0.0f;
        #pragma unroll
        for (int off = 4; off > 0; off >>= 1)
            v += __shfl_down_sync(0xFFFFFFFFu, v, off);
        if (lane == 0) g_partials[blockIdx.x] = v;
    }
}

__global__ void __launch_bounds__(1024, 1)
rdl_final_kernel(float* __restrict__ out, float inv_n)
{
    float acc = 0.0f;
    for (int i = threadIdx.x; i < NBLOCKS; i += 1024)
        acc += g_partials[i];

    #pragma unroll
    for (int off = 16; off > 0; off >>= 1)
        acc += __shfl_down_sync(0xFFFFFFFFu, acc, off);

    __shared__ float s_warp[32];
    int lane = threadIdx.x & 31;
    int wid  = threadIdx.x >> 5;
    if (lane == 0) s_warp[wid] = acc;
    __syncthreads();

    if (wid == 0) {
        float v = (lane < 32) ? s_warp[lane] : 0.0f;
        #pragma unroll
        for (int off = 16; off > 0; off >>= 1)
            v += __shfl_down_sync(0xFFFFFFFFu, v, off);
        if (lane == 0) out[0] = v * inv_n;
    }
}

extern "C" void kernel_launch(void* const* d_in, const int* in_sizes, int n_in,
                              void* d_out, int out_size)
{
    const float* x = (const float*)d_in[0];
    const float* y = (const float*)d_in[1];
    float* out = (float*)d_out;

    int n  = in_sizes[0];       // 33554432, divisible by 4
    int n4 = n >> 2;

    rdl_partial_kernel<<<NBLOCKS, NTHREADS>>>(x, y, n4);
    rdl_final_kernel<<<1, 1024>>>(out, 1.0f / (float)n);
}